// round 14
// baseline (speedup 1.0000x reference)
#include <cuda_runtime.h>
#include <cuda_bf16.h>

// Problem constants (shapes fixed by dataset)
#define NFEAT 256
#define NHID  256
#define NOUT  128
#define MAX_NODES 50000

// Scratch (no cudaMalloc allowed)
__device__ float g_sup1[(size_t)MAX_NODES * NHID];   // X @ W1
__device__ float g_agg1[(size_t)MAX_NODES * NHID];   // segment_sum(sup1[src])
__device__ float g_sup2[(size_t)MAX_NODES * NOUT];   // relu(agg1) @ W2

typedef unsigned long long u64;

// Packed dual-fp32 FMA: d.lo += a.lo*b.lo ; d.hi += a.hi*b.hi  (sm_10x FFMA2)
__device__ __forceinline__ void ffma2(u64& d, u64 a, u64 b) {
    asm("fma.rn.f32x2 %0, %1, %2, %0;" : "+l"(d) : "l"(a), "l"(b));
}

__device__ __forceinline__ float2 unpack2(u64 v) {
    float2 f;
    asm("mov.b64 {%0, %1}, %2;" : "=f"(f.x), "=f"(f.y) : "l"(v));
    return f;
}

// ---------------------------------------------------------------------------
// 128x128x16 fp32 GEMM using packed f32x2 FMAs.
// C[M,N] = op(A)[M,K] @ B[K,N].  256 threads, 8x8 micro-tile per thread
// (4 M-pairs x 8 N), double-buffered smem. B is stored lane-duplicated in
// smem ((b,b) float2) so the FFMA2 b-operand needs no pack instructions;
// the a-operand pairs are contiguous M-pairs read directly from smem.
// ---------------------------------------------------------------------------
template<bool RELU_A>
__global__ __launch_bounds__(256, 2)
void sgemm2_kernel(const float* __restrict__ A, const float* __restrict__ B,
                   float* __restrict__ C, int M, int N, int K)
{
    __shared__ __align__(16) float  As[2][16][128];   // transposed A: As[k][m]
    __shared__ __align__(16) float2 Bs[2][16][128];   // duplicated B: (b,b)

    const int tid = threadIdx.x;
    const int m0  = blockIdx.x * 128;
    const int n0  = blockIdx.y * 128;

    const int tr = tid >> 4;            // 0..15 -> M rows tr*8 .. tr*8+7
    const int tc = tid & 15;            // 0..15 -> N cols tc*8 .. tc*8+7

    // A tile loader: 128 rows x 16 cols; each thread 2 float4 in one row
    const int ar = tid >> 1;            // 0..127
    const int ac = (tid & 1) * 8;       // 0 or 8
    // B tile loader: 16 rows x 128 cols; each thread float4 in rows br, br+8
    const int br = tid >> 5;            // 0..7
    const int bc = (tid & 31) * 4;      // 0..124

    u64 acc[4][8];
#pragma unroll
    for (int i = 0; i < 4; i++)
#pragma unroll
        for (int j = 0; j < 8; j++) acc[i][j] = 0ull;

    const int T = K >> 4;               // K/16 tiles
    const int gm = m0 + ar;

    float4 pa0, pa1, pb0, pb1;

    // ---- prefetch helpers ----
    auto ldg_tile = [&](int k0) {
        pa0 = make_float4(0.f, 0.f, 0.f, 0.f);
        pa1 = pa0;
        if (gm < M) {
            const float* p = A + (long long)gm * K + k0 + ac;
            pa0 = *reinterpret_cast<const float4*>(p);
            pa1 = *reinterpret_cast<const float4*>(p + 4);
        }
        if (RELU_A) {
            pa0.x = fmaxf(pa0.x, 0.f); pa0.y = fmaxf(pa0.y, 0.f);
            pa0.z = fmaxf(pa0.z, 0.f); pa0.w = fmaxf(pa0.w, 0.f);
            pa1.x = fmaxf(pa1.x, 0.f); pa1.y = fmaxf(pa1.y, 0.f);
            pa1.z = fmaxf(pa1.z, 0.f); pa1.w = fmaxf(pa1.w, 0.f);
        }
        const float* q0 = B + (long long)(k0 + br) * N + n0 + bc;
        const float* q1 = B + (long long)(k0 + br + 8) * N + n0 + bc;
        pb0 = *reinterpret_cast<const float4*>(q0);
        pb1 = *reinterpret_cast<const float4*>(q1);
    };
    auto sts_tile = [&](int buf) {
        // A transposed
        As[buf][ac + 0][ar] = pa0.x;  As[buf][ac + 1][ar] = pa0.y;
        As[buf][ac + 2][ar] = pa0.z;  As[buf][ac + 3][ar] = pa0.w;
        As[buf][ac + 4][ar] = pa1.x;  As[buf][ac + 5][ar] = pa1.y;
        As[buf][ac + 6][ar] = pa1.z;  As[buf][ac + 7][ar] = pa1.w;
        // B duplicated pairs (two float2 per 16B store)
        float4* r0 = reinterpret_cast<float4*>(&Bs[buf][br][bc]);
        r0[0] = make_float4(pb0.x, pb0.x, pb0.y, pb0.y);
        r0[1] = make_float4(pb0.z, pb0.z, pb0.w, pb0.w);
        float4* r1 = reinterpret_cast<float4*>(&Bs[buf][br + 8][bc]);
        r1[0] = make_float4(pb1.x, pb1.x, pb1.y, pb1.y);
        r1[1] = make_float4(pb1.z, pb1.z, pb1.w, pb1.w);
    };

    ldg_tile(0);
    sts_tile(0);
    __syncthreads();

    for (int t = 0; t < T; t++) {
        const int cur = t & 1;
        if (t + 1 < T) ldg_tile((t + 1) << 4);

#pragma unroll
        for (int k = 0; k < 16; k++) {
            u64 aa[4];
            const ulonglong2 a01 = *reinterpret_cast<const ulonglong2*>(&As[cur][k][tr * 8]);
            const ulonglong2 a23 = *reinterpret_cast<const ulonglong2*>(&As[cur][k][tr * 8 + 4]);
            aa[0] = a01.x; aa[1] = a01.y; aa[2] = a23.x; aa[3] = a23.y;

            u64 bb[8];
            const ulonglong2* bp = reinterpret_cast<const ulonglong2*>(&Bs[cur][k][tc * 8]);
#pragma unroll
            for (int q = 0; q < 4; q++) {
                const ulonglong2 t2 = bp[q];
                bb[2 * q] = t2.x; bb[2 * q + 1] = t2.y;
            }
#pragma unroll
            for (int i = 0; i < 4; i++)
#pragma unroll
                for (int j = 0; j < 8; j++)
                    ffma2(acc[i][j], aa[i], bb[j]);
        }

        if (t + 1 < T) sts_tile(cur ^ 1);
        __syncthreads();
    }

    // ---- store C ----
#pragma unroll
    for (int i2 = 0; i2 < 4; i2++) {
        float lo[8], hi[8];
#pragma unroll
        for (int j = 0; j < 8; j++) {
            const float2 f = unpack2(acc[i2][j]);
            lo[j] = f.x; hi[j] = f.y;
        }
        const int r0 = m0 + tr * 8 + 2 * i2;
        if (r0 < M) {
            float* p = C + (long long)r0 * N + n0 + tc * 8;
            *reinterpret_cast<float4*>(p)     = make_float4(lo[0], lo[1], lo[2], lo[3]);
            *reinterpret_cast<float4*>(p + 4) = make_float4(lo[4], lo[5], lo[6], lo[7]);
        }
        if (r0 + 1 < M) {
            float* p = C + (long long)(r0 + 1) * N + n0 + tc * 8;
            *reinterpret_cast<float4*>(p)     = make_float4(hi[0], hi[1], hi[2], hi[3]);
            *reinterpret_cast<float4*>(p + 4) = make_float4(hi[4], hi[5], hi[6], hi[7]);
        }
    }
}

// ---------------------------------------------------------------------------
// Edge scatter-add via red.global.add.v4.f32 (at the L2 atomic-slice ceiling)
// ---------------------------------------------------------------------------
template<int V, int LOGV>
__global__ __launch_bounds__(256)
void scatter_kernel(const float* __restrict__ sup,
                    const int* __restrict__ src,
                    const int* __restrict__ dst,
                    float* __restrict__ out, int n_edges)
{
    const int total  = n_edges << LOGV;
    const int stride = gridDim.x * blockDim.x;
    const float4* sup4 = reinterpret_cast<const float4*>(sup);

    for (int i = blockIdx.x * blockDim.x + threadIdx.x; i < total; i += stride) {
        const int e = i >> LOGV;
        const int j = i & (V - 1);
        const int s = __ldg(src + e);
        const int d = __ldg(dst + e);
        const float4 v = __ldg(sup4 + (long long)s * V + j);
        float* p = out + (((long long)d * V + j) << 2);
        asm volatile("red.global.add.v4.f32 [%0], {%1, %2, %3, %4};"
                     :: "l"(p), "f"(v.x), "f"(v.y), "f"(v.z), "f"(v.w)
                     : "memory");
    }
}

extern "C" void kernel_launch(void* const* d_in, const int* in_sizes, int n_in,
                              void* d_out, int out_size)
{
    const float* x    = (const float*)d_in[0];   // [N, 256]
    const float* w1   = (const float*)d_in[1];   // [256, 256]
    const float* w2   = (const float*)d_in[2];   // [256, 128]
    const int*   esrc = (const int*)d_in[3];     // [E]
    const int*   edst = (const int*)d_in[4];     // [E]

    const int M = in_sizes[0] / NFEAT;   // 50000 nodes
    const int E = in_sizes[3];           // 800000 edges

    float *sup1, *agg1, *sup2;
    cudaGetSymbolAddress((void**)&sup1, g_sup1);
    cudaGetSymbolAddress((void**)&agg1, g_agg1);
    cudaGetSymbolAddress((void**)&sup2, g_sup2);

    cudaMemsetAsync(agg1, 0, (size_t)M * NHID * sizeof(float));
    cudaMemsetAsync(d_out, 0, (size_t)out_size * sizeof(float));

    const dim3 tb(256);
    const int mblk = (M + 127) / 128;

    // layer 1: sup1 = X @ W1
    sgemm2_kernel<false><<<dim3(mblk, NHID / 128), tb>>>(x, w1, sup1, M, NHID, NFEAT);
    // agg1[dst] += sup1[src]
    scatter_kernel<64, 6><<<4736, 256>>>(sup1, esrc, edst, agg1, E);
    // layer 2: sup2 = relu(agg1) @ W2
    sgemm2_kernel<true><<<dim3(mblk, NOUT / 128), tb>>>(agg1, w2, sup2, M, NOUT, NHID);
    // out[dst] += sup2[src]
    scatter_kernel<32, 5><<<4736, 256>>>(sup2, esrc, edst, (float*)d_out, E);
}

// round 15
// speedup vs baseline: 1.0021x; 1.0021x over previous
#include <cuda_runtime.h>
#include <cuda_bf16.h>

// Problem constants (shapes fixed by dataset)
#define NFEAT 256
#define NHID  256
#define NOUT  128
#define MAX_NODES 50000

// Scratch (no cudaMalloc allowed)
__device__ float g_sup1[(size_t)MAX_NODES * NHID];   // X @ W1
__device__ float g_agg1[(size_t)MAX_NODES * NHID];   // segment_sum(sup1[src])
__device__ float g_sup2[(size_t)MAX_NODES * NOUT];   // relu(agg1) @ W2

typedef unsigned long long u64;

// Packed dual-fp32 FMA: d.lo += a.lo*b.lo ; d.hi += a.hi*b.hi  (sm_10x FFMA2)
__device__ __forceinline__ void ffma2(u64& d, u64 a, u64 b) {
    asm("fma.rn.f32x2 %0, %1, %2, %0;" : "+l"(d) : "l"(a), "l"(b));
}

__device__ __forceinline__ float2 unpack2(u64 v) {
    float2 f;
    asm("mov.b64 {%0, %1}, %2;" : "=f"(f.x), "=f"(f.y) : "l"(v));
    return f;
}

// ---------------------------------------------------------------------------
// 128x128x16 fp32 GEMM using packed f32x2 FMAs.
// C[M,N] = op(A)[M,K] @ B[K,N].  256 threads, 8x8 micro-tile per thread
// (4 M-pairs x 8 N), double-buffered smem. B is stored lane-duplicated in
// smem ((b,b) float2) so the FFMA2 b-operand needs no pack instructions;
// the a-operand pairs are contiguous M-pairs read directly from smem.
// ---------------------------------------------------------------------------
template<bool RELU_A>
__global__ __launch_bounds__(256, 2)
void sgemm2_kernel(const float* __restrict__ A, const float* __restrict__ B,
                   float* __restrict__ C, int M, int N, int K)
{
    __shared__ __align__(16) float  As[2][16][128];   // transposed A: As[k][m]
    __shared__ __align__(16) float2 Bs[2][16][128];   // duplicated B: (b,b)

    const int tid = threadIdx.x;
    const int m0  = blockIdx.x * 128;
    const int n0  = blockIdx.y * 128;

    const int tr = tid >> 4;            // 0..15 -> M rows tr*8 .. tr*8+7
    const int tc = tid & 15;            // 0..15 -> N cols tc*8 .. tc*8+7

    // A tile loader: 128 rows x 16 cols; each thread 2 float4 in one row
    const int ar = tid >> 1;            // 0..127
    const int ac = (tid & 1) * 8;       // 0 or 8
    // B tile loader: 16 rows x 128 cols; each thread float4 in rows br, br+8
    const int br = tid >> 5;            // 0..7
    const int bc = (tid & 31) * 4;      // 0..124

    u64 acc[4][8];
#pragma unroll
    for (int i = 0; i < 4; i++)
#pragma unroll
        for (int j = 0; j < 8; j++) acc[i][j] = 0ull;

    const int T = K >> 4;               // K/16 tiles
    const int gm = m0 + ar;

    float4 pa0, pa1, pb0, pb1;

    // ---- prefetch helpers ----
    auto ldg_tile = [&](int k0) {
        pa0 = make_float4(0.f, 0.f, 0.f, 0.f);
        pa1 = pa0;
        if (gm < M) {
            const float* p = A + (long long)gm * K + k0 + ac;
            pa0 = *reinterpret_cast<const float4*>(p);
            pa1 = *reinterpret_cast<const float4*>(p + 4);
        }
        if (RELU_A) {
            pa0.x = fmaxf(pa0.x, 0.f); pa0.y = fmaxf(pa0.y, 0.f);
            pa0.z = fmaxf(pa0.z, 0.f); pa0.w = fmaxf(pa0.w, 0.f);
            pa1.x = fmaxf(pa1.x, 0.f); pa1.y = fmaxf(pa1.y, 0.f);
            pa1.z = fmaxf(pa1.z, 0.f); pa1.w = fmaxf(pa1.w, 0.f);
        }
        const float* q0 = B + (long long)(k0 + br) * N + n0 + bc;
        const float* q1 = B + (long long)(k0 + br + 8) * N + n0 + bc;
        pb0 = *reinterpret_cast<const float4*>(q0);
        pb1 = *reinterpret_cast<const float4*>(q1);
    };
    auto sts_tile = [&](int buf) {
        // A transposed
        As[buf][ac + 0][ar] = pa0.x;  As[buf][ac + 1][ar] = pa0.y;
        As[buf][ac + 2][ar] = pa0.z;  As[buf][ac + 3][ar] = pa0.w;
        As[buf][ac + 4][ar] = pa1.x;  As[buf][ac + 5][ar] = pa1.y;
        As[buf][ac + 6][ar] = pa1.z;  As[buf][ac + 7][ar] = pa1.w;
        // B duplicated pairs (two float2 per 16B store)
        float4* r0 = reinterpret_cast<float4*>(&Bs[buf][br][bc]);
        r0[0] = make_float4(pb0.x, pb0.x, pb0.y, pb0.y);
        r0[1] = make_float4(pb0.z, pb0.z, pb0.w, pb0.w);
        float4* r1 = reinterpret_cast<float4*>(&Bs[buf][br + 8][bc]);
        r1[0] = make_float4(pb1.x, pb1.x, pb1.y, pb1.y);
        r1[1] = make_float4(pb1.z, pb1.z, pb1.w, pb1.w);
    };

    ldg_tile(0);
    sts_tile(0);
    __syncthreads();

    for (int t = 0; t < T; t++) {
        const int cur = t & 1;
        if (t + 1 < T) ldg_tile((t + 1) << 4);

#pragma unroll
        for (int k = 0; k < 16; k++) {
            u64 aa[4];
            const ulonglong2 a01 = *reinterpret_cast<const ulonglong2*>(&As[cur][k][tr * 8]);
            const ulonglong2 a23 = *reinterpret_cast<const ulonglong2*>(&As[cur][k][tr * 8 + 4]);
            aa[0] = a01.x; aa[1] = a01.y; aa[2] = a23.x; aa[3] = a23.y;

            u64 bb[8];
            const ulonglong2* bp = reinterpret_cast<const ulonglong2*>(&Bs[cur][k][tc * 8]);
#pragma unroll
            for (int q = 0; q < 4; q++) {
                const ulonglong2 t2 = bp[q];
                bb[2 * q] = t2.x; bb[2 * q + 1] = t2.y;
            }
#pragma unroll
            for (int i = 0; i < 4; i++)
#pragma unroll
                for (int j = 0; j < 8; j++)
                    ffma2(acc[i][j], aa[i], bb[j]);
        }

        if (t + 1 < T) sts_tile(cur ^ 1);
        __syncthreads();
    }

    // ---- store C ----
#pragma unroll
    for (int i2 = 0; i2 < 4; i2++) {
        float lo[8], hi[8];
#pragma unroll
        for (int j = 0; j < 8; j++) {
            const float2 f = unpack2(acc[i2][j]);
            lo[j] = f.x; hi[j] = f.y;
        }
        const int r0 = m0 + tr * 8 + 2 * i2;
        if (r0 < M) {
            float* p = C + (long long)r0 * N + n0 + tc * 8;
            *reinterpret_cast<float4*>(p)     = make_float4(lo[0], lo[1], lo[2], lo[3]);
            *reinterpret_cast<float4*>(p + 4) = make_float4(lo[4], lo[5], lo[6], lo[7]);
        }
        if (r0 + 1 < M) {
            float* p = C + (long long)(r0 + 1) * N + n0 + tc * 8;
            *reinterpret_cast<float4*>(p)     = make_float4(hi[0], hi[1], hi[2], hi[3]);
            *reinterpret_cast<float4*>(p + 4) = make_float4(hi[4], hi[5], hi[6], hi[7]);
        }
    }
}

// ---------------------------------------------------------------------------
// Edge scatter-add via red.global.add.v4.f32 (at the L2 atomic-slice ceiling)
// ---------------------------------------------------------------------------
template<int V, int LOGV>
__global__ __launch_bounds__(256)
void scatter_kernel(const float* __restrict__ sup,
                    const int* __restrict__ src,
                    const int* __restrict__ dst,
                    float* __restrict__ out, int n_edges)
{
    const int total  = n_edges << LOGV;
    const int stride = gridDim.x * blockDim.x;
    const float4* sup4 = reinterpret_cast<const float4*>(sup);

    for (int i = blockIdx.x * blockDim.x + threadIdx.x; i < total; i += stride) {
        const int e = i >> LOGV;
        const int j = i & (V - 1);
        const int s = __ldg(src + e);
        const int d = __ldg(dst + e);
        const float4 v = __ldg(sup4 + (long long)s * V + j);
        float* p = out + (((long long)d * V + j) << 2);
        asm volatile("red.global.add.v4.f32 [%0], {%1, %2, %3, %4};"
                     :: "l"(p), "f"(v.x), "f"(v.y), "f"(v.z), "f"(v.w)
                     : "memory");
    }
}

extern "C" void kernel_launch(void* const* d_in, const int* in_sizes, int n_in,
                              void* d_out, int out_size)
{
    const float* x    = (const float*)d_in[0];   // [N, 256]
    const float* w1   = (const float*)d_in[1];   // [256, 256]
    const float* w2   = (const float*)d_in[2];   // [256, 128]
    const int*   esrc = (const int*)d_in[3];     // [E]
    const int*   edst = (const int*)d_in[4];     // [E]

    const int M = in_sizes[0] / NFEAT;   // 50000 nodes
    const int E = in_sizes[3];           // 800000 edges

    float *sup1, *agg1, *sup2;
    cudaGetSymbolAddress((void**)&sup1, g_sup1);
    cudaGetSymbolAddress((void**)&agg1, g_agg1);
    cudaGetSymbolAddress((void**)&sup2, g_sup2);

    cudaMemsetAsync(agg1, 0, (size_t)M * NHID * sizeof(float));
    cudaMemsetAsync(d_out, 0, (size_t)out_size * sizeof(float));

    const dim3 tb(256);
    const int mblk = (M + 127) / 128;

    // layer 1: sup1 = X @ W1
    sgemm2_kernel<false><<<dim3(mblk, NHID / 128), tb>>>(x, w1, sup1, M, NHID, NFEAT);
    // agg1[dst] += sup1[src]
    scatter_kernel<64, 6><<<4736, 256>>>(sup1, esrc, edst, agg1, E);
    // layer 2: sup2 = relu(agg1) @ W2
    sgemm2_kernel<true><<<dim3(mblk, NOUT / 128), tb>>>(agg1, w2, sup2, M, NOUT, NHID);
    // out[dst] += sup2[src]
    scatter_kernel<32, 5><<<4736, 256>>>(sup2, esrc, edst, (float*)d_out, E);
}